// round 5
// baseline (speedup 1.0000x reference)
#include <cuda_runtime.h>
#include <math.h>

#define NBLK  128
#define NTHR  512
#define NWARP (NTHR / 32)
#define NCAND (NBLK * 8)

struct Pair { float v; int i; };

__device__ Pair g_pos[NCAND];
__device__ Pair g_neg[NCAND];
__device__ unsigned int g_count = 0;

__device__ __forceinline__ bool better(Pair a, Pair b) {
    // jax.lax.top_k order: larger value first, ties -> lower index
    return (a.v > b.v) || (a.v == b.v && a.i < b.i);
}

// compare-exchange: better element ends in x
__device__ __forceinline__ void cx(Pair& x, Pair& y) {
    if (better(y, x)) { Pair t = x; x = y; y = t; }
}

__device__ __forceinline__ void pinit(Pair* t) {
#pragma unroll
    for (int k = 0; k < 8; k++) { t[k].v = -INFINITY; t[k].i = 0x7fffffff; }
}

// t sorted desc; insert candidate keeping top-8 (hot path: 1 compare)
__device__ __forceinline__ void insert8(Pair* t, float v, int i) {
    Pair c; c.v = v; c.i = i;
    if (!better(c, t[7])) return;
    t[7] = c;
#pragma unroll
    for (int k = 7; k > 0; --k) cx(t[k - 1], t[k]);
}

// sort a bitonic (desc-then-asc) 8-seq into desc: static 3-stage network
__device__ __forceinline__ void bitonic8(Pair* t) {
#pragma unroll
    for (int k = 0; k < 4; k++) cx(t[k], t[k + 4]);
#pragma unroll
    for (int h = 0; h < 8; h += 4) { cx(t[h], t[h + 2]); cx(t[h + 1], t[h + 3]); }
#pragma unroll
    for (int p = 0; p < 8; p += 2) cx(t[p], t[p + 1]);
}

// one xor-merge round: exchange sorted-8 lists with partner lane, keep top-8.
// Batcher halver: c[k] = max(a[k], b[7-k]) is the top-8 multiset and bitonic.
__device__ __forceinline__ void merge_step(Pair* t, int off) {
    Pair b[8];
#pragma unroll
    for (int k = 0; k < 8; k++) {              // 16 independent shfls
        b[k].v = __shfl_xor_sync(0xffffffffu, t[k].v, off);
        b[k].i = __shfl_xor_sync(0xffffffffu, t[k].i, off);
    }
#pragma unroll
    for (int k = 0; k < 8; k++) {
        Pair r = b[7 - k];
        if (better(r, t[k])) t[k] = r;
    }
    bitonic8(t);
}

__device__ __forceinline__ void warp_merge1(Pair* t) {
#pragma unroll
    for (int off = 1; off < 32; off <<= 1) merge_step(t, off);
}

// merge two lists per call site for ILP (pos/neg interleave)
__device__ __forceinline__ void warp_merge2(Pair* tp, Pair* tn) {
#pragma unroll
    for (int off = 1; off < 32; off <<= 1) { merge_step(tp, off); merge_step(tn, off); }
}

__global__ void __launch_bounds__(NTHR)
ins_fused(const float* __restrict__ h, const float* __restrict__ A,
          const float* __restrict__ W, const float* __restrict__ b,
          const int* __restrict__ bag, float* __restrict__ out,
          int N, int D, int C, int out_size)
{
    __shared__ Pair s_pos[NWARP * 8];
    __shared__ Pair s_neg[NWARP * 8];
    __shared__ int  idx16[16];
    __shared__ bool isLast;

    const int tid  = threadIdx.x;
    const int lane = tid & 31, warp = tid >> 5;

    int col = C - 1;
    if (bag) { int raw = bag[0]; if (raw >= 0 && raw < C) col = raw; }

    // L2 prefetch of W & b from block 0 (last block's GEMM will hit L2)
    if (blockIdx.x == 0 && warp == NWARP - 1) {
        const char* wp = (const char*)W;
        long long wbytes = (long long)D * C * 4;
        for (long long o = lane * 128; o < wbytes; o += 32 * 128)
            asm volatile("prefetch.global.L2 [%0];" :: "l"(wp + o));
        if (lane == 0) asm volatile("prefetch.global.L2 [%0];" :: "l"((const char*)b));
    }

    // ---------- phase 1: sweep A ----------
    Pair tp[8], tn[8];
    pinit(tp); pinit(tn);

    const int stride = gridDim.x * blockDim.x;
    if (C == 2 && ((N & 1) == 0)) {
        const float4* A4 = (const float4*)A;   // one float4 = rows {2j, 2j+1}
        const int M = N >> 1;
        for (int j = blockIdx.x * blockDim.x + tid; j < M; j += 4 * stride) {
            int j1 = j + stride, j2 = j + 2 * stride, j3 = j + 3 * stride;
            bool p1 = j1 < M, p2 = j2 < M, p3 = j3 < M;
            float4 x0 = A4[j];
            float4 x1 = p1 ? A4[j1] : make_float4(0.f, 0.f, 0.f, 0.f);
            float4 x2 = p2 ? A4[j2] : make_float4(0.f, 0.f, 0.f, 0.f);
            float4 x3 = p3 ? A4[j3] : make_float4(0.f, 0.f, 0.f, 0.f);

            float v0 = col ? x0.y : x0.x, v1 = col ? x0.w : x0.z;
            insert8(tp,  v0, 2 * j);     insert8(tn, -v0, 2 * j);
            insert8(tp,  v1, 2 * j + 1); insert8(tn, -v1, 2 * j + 1);
            if (p1) {
                float a = col ? x1.y : x1.x, c = col ? x1.w : x1.z;
                insert8(tp,  a, 2 * j1);     insert8(tn, -a, 2 * j1);
                insert8(tp,  c, 2 * j1 + 1); insert8(tn, -c, 2 * j1 + 1);
            }
            if (p2) {
                float a = col ? x2.y : x2.x, c = col ? x2.w : x2.z;
                insert8(tp,  a, 2 * j2);     insert8(tn, -a, 2 * j2);
                insert8(tp,  c, 2 * j2 + 1); insert8(tn, -c, 2 * j2 + 1);
            }
            if (p3) {
                float a = col ? x3.y : x3.x, c = col ? x3.w : x3.z;
                insert8(tp,  a, 2 * j3);     insert8(tn, -a, 2 * j3);
                insert8(tp,  c, 2 * j3 + 1); insert8(tn, -c, 2 * j3 + 1);
            }
        }
    } else {
        for (int i = blockIdx.x * blockDim.x + tid; i < N; i += stride) {
            float v = __ldg(A + (long long)i * C + col);
            insert8(tp,  v, i);
            insert8(tn, -v, i);
        }
    }

    // ---------- phase 2: block reduce ----------
    warp_merge2(tp, tn);
    if (lane == 0) {
#pragma unroll
        for (int k = 0; k < 8; k++) { s_pos[warp * 8 + k] = tp[k]; s_neg[warp * 8 + k] = tn[k]; }
    }
    __syncthreads();

    if (warp < 2) {
        Pair t[8];
        const Pair* src = (warp == 0) ? s_pos : s_neg;
        if (lane < NWARP) {
#pragma unroll
            for (int k = 0; k < 8; k++) t[k] = src[lane * 8 + k];
        } else pinit(t);
        warp_merge1(t);
        if (lane == 0) {
            Pair* dst = (warp == 0) ? (g_pos + blockIdx.x * 8) : (g_neg + blockIdx.x * 8);
#pragma unroll
            for (int k = 0; k < 8; k++) dst[k] = t[k];
            __threadfence();
        }
    }
    __syncthreads();
    if (tid == 0) isLast = (atomicAdd(&g_count, 1u) == (unsigned)(gridDim.x - 1));
    __syncthreads();
    if (!isLast) return;
    if (tid == 0) { g_count = 0; __threadfence(); }

    // ---------- phase 3 (last block only): final reduce ----------
    {
        const float4* src = (const float4*)((warp < NWARP / 2) ? g_pos : g_neg);
        const int ht = (warp < NWARP / 2) ? tid : tid - (NTHR / 2);  // 0..255
        const int npair4 = NCAND / 2;                                // 512
        Pair t[8]; pinit(t);
#pragma unroll 2
        for (int j = ht; j < npair4; j += NTHR / 2) {
            float4 f = src[j];
            insert8(t, f.x, __float_as_int(f.y));
            insert8(t, f.z, __float_as_int(f.w));
        }
        warp_merge1(t);
        if (lane == 0) {
            Pair* dst = (warp < NWARP / 2) ? (s_pos + warp * 8)
                                           : (s_neg + (warp - NWARP / 2) * 8);
#pragma unroll
            for (int k = 0; k < 8; k++) dst[k] = t[k];
        }
    }
    __syncthreads();
    if (warp < 2) {
        Pair t[8];
        const Pair* src = (warp == 0) ? s_pos : s_neg;
        if (lane < NWARP / 2) {
#pragma unroll
            for (int k = 0; k < 8; k++) t[k] = src[lane * 8 + k];
        } else pinit(t);
        warp_merge1(t);
        if (lane == 0) {
#pragma unroll
            for (int k = 0; k < 8; k++) idx16[((warp == 0) ? 0 : 8) + k] = t[k].i;
        }
    }
    __syncthreads();

    // labels
    if (tid < 16 && tid < out_size) out[tid] = (tid < 8) ? 1.0f : 0.0f;

    // ---------- phase 4: gather GEMM + softmax ----------
    if (C == 2 && (D & 3) == 0) {
        if (warp < 16) {
            int idx = idx16[warp];
            if (idx < 0 || idx >= N) idx = 0;
            const float4* h4 = (const float4*)(h + (long long)idx * D);
            const float4* W4 = (const float4*)W;
            const int D4 = D >> 2;
            float a0 = 0.f, a1 = 0.f;
#pragma unroll 4
            for (int k = lane; k < D4; k += 32) {
                float4 x  = h4[k];
                float4 w0 = W4[2 * k];
                float4 w1 = W4[2 * k + 1];
                a0 = fmaf(x.x, w0.x, fmaf(x.y, w0.z, fmaf(x.z, w1.x, fmaf(x.w, w1.z, a0))));
                a1 = fmaf(x.x, w0.y, fmaf(x.y, w0.w, fmaf(x.z, w1.y, fmaf(x.w, w1.w, a1))));
            }
#pragma unroll
            for (int off = 16; off > 0; off >>= 1) {
                a0 += __shfl_xor_sync(0xffffffffu, a0, off);
                a1 += __shfl_xor_sync(0xffffffffu, a1, off);
            }
            if (lane == 0) {
                float l0 = a0 + b[0], l1 = a1 + b[1];
                float m  = fmaxf(l0, l1);
                float e0 = __expf(l0 - m), e1 = __expf(l1 - m);
                float inv = 1.f / (e0 + e1);
                if (16 + 2 * warp < out_size) out[16 + 2 * warp] = e0 * inv;
                if (17 + 2 * warp < out_size) out[17 + 2 * warp] = e1 * inv;
            }
        }
    } else {
        for (int row = warp; row < 16; row += NWARP) {
            int idx = idx16[row];
            if (idx < 0 || idx >= N) idx = 0;
            const float* hr = h + (long long)idx * D;
            float m = -INFINITY, sum = 0.f;
            for (int c = 0; c < C; ++c) {
                float a = 0.f;
                for (int d = lane; d < D; d += 32)
                    a = fmaf(__ldg(hr + d), __ldg(W + (long long)d * C + c), a);
#pragma unroll
                for (int off = 16; off > 0; off >>= 1)
                    a += __shfl_xor_sync(0xffffffffu, a, off);
                a += b[c];
                m = fmaxf(m, a);
            }
            for (int c = 0; c < C; ++c) {
                float a = 0.f;
                for (int d = lane; d < D; d += 32)
                    a = fmaf(__ldg(hr + d), __ldg(W + (long long)d * C + c), a);
#pragma unroll
                for (int off = 16; off > 0; off >>= 1)
                    a += __shfl_xor_sync(0xffffffffu, a, off);
                a += b[c];
                sum += __expf(a - m);
            }
            for (int c = 0; c < C; ++c) {
                float a = 0.f;
                for (int d = lane; d < D; d += 32)
                    a = fmaf(__ldg(hr + d), __ldg(W + (long long)d * C + c), a);
#pragma unroll
                for (int off = 16; off > 0; off >>= 1)
                    a += __shfl_xor_sync(0xffffffffu, a, off);
                a += b[c];
                int o = 16 + row * C + c;
                if (lane == 0 && o < out_size) out[o] = __expf(a - m) / sum;
            }
        }
    }
}

extern "C" void kernel_launch(void* const* d_in, const int* in_sizes, int n_in,
                              void* d_out, int out_size)
{
    // Identify inputs by element count:
    //   h: N*D (largest), A: N*C (2nd), W: D*C, b: C, bag: 1 (optional)
    int ih = -1, ia = -1, iw = -1, ib = -1, ibag = -1;
    long long best1 = -1, best2 = -1;
    for (int k = 0; k < n_in; k++) {
        long long sz = in_sizes[k];
        if (sz > best1) { best2 = best1; ia = ih; best1 = sz; ih = k; }
        else if (sz > best2) { best2 = sz; ia = k; }
    }
    long long wbest = -1, bbest = -1;
    for (int k = 0; k < n_in; k++) {
        if (k == ih || k == ia) continue;
        long long sz = in_sizes[k];
        if (sz == 1 && ibag < 0) { ibag = k; continue; }
        if (sz > wbest) { bbest = wbest; ib = iw; wbest = sz; iw = k; }
        else if (sz > bbest) { bbest = sz; ib = k; }
    }

    const float* h   = (const float*)d_in[ih];
    const float* A   = (const float*)d_in[ia];
    const float* W   = (const float*)d_in[iw];
    const float* b   = (const float*)d_in[ib];
    const int*   bag = (ibag >= 0) ? (const int*)d_in[ibag] : nullptr;

    int C = in_sizes[ib];
    int D = in_sizes[iw] / C;
    int N = (int)((long long)in_sizes[ih] / D);

    ins_fused<<<NBLK, NTHR>>>(h, A, W, b, bag, (float*)d_out, N, D, C, out_size);
}